// round 10
// baseline (speedup 1.0000x reference)
#include <cuda_runtime.h>

// Problem constants
#define BB 8
#define CC 256
#define NN 65536            // 256*256 spatial
#define TT 64               // pixels per tile (iter 0)
#define T2 32               // pixels per tile (iters 1,2)
#define TILES0 1024         // tiles/batch iter0
#define TILES2 2048         // tiles/batch iters 1,2
#define BPB0 38
#define TPB0 27
#define GRID0 (BB * BPB0)   // 304 = 2/SM
#define BPB2 57
#define TPB2 36
#define GRID2 (BB * BPB2)   // 456 = 3/SM
#define THREADS 256

// Output layout (flat float32 concat of reference returns)
#define OFF_LABELS  512
#define OFF_ONEHOT  (512 + BB * NN)              // 524800
#define OFF_CURDIST (OFF_ONEHOT + 2LL * BB * NN) // 1573376

// -------- device scratch (no allocations; zero-initialized) --------
__device__ float g_sums[BB * 2 * CC];   // [b][k][c] (re-zeroed by tails)
__device__ float g_counts[BB * 2];      // [b][k]
__device__ float g_tot[BB * CC];        // iteration-invariant channel totals
__device__ float g_centers[2 * CC];
__device__ float g_cn[2 * CC];          // normalized, interleaved [c][k]
__device__ unsigned char g_labels[(long long)BB * NN];
__device__ float g_curdist;
__device__ int g_done;                  // reset by k_final
__device__ unsigned g_ticket;           // self-resetting

// -------- block reduce of 4 floats (256 threads) --------
__device__ __forceinline__ float4 blockReduce4(float4 v, float* scr) {
#pragma unroll
    for (int o = 16; o > 0; o >>= 1) {
        v.x += __shfl_down_sync(0xffffffffu, v.x, o);
        v.y += __shfl_down_sync(0xffffffffu, v.y, o);
        v.z += __shfl_down_sync(0xffffffffu, v.z, o);
        v.w += __shfl_down_sync(0xffffffffu, v.w, o);
    }
    int wid = threadIdx.x >> 5, lane = threadIdx.x & 31;
    __syncthreads();
    if (lane == 0) {
        scr[wid * 4 + 0] = v.x; scr[wid * 4 + 1] = v.y;
        scr[wid * 4 + 2] = v.z; scr[wid * 4 + 3] = v.w;
    }
    __syncthreads();
    if (threadIdx.x == 0) {
        float a = 0.f, b = 0.f, c = 0.f, d = 0.f;
#pragma unroll
        for (int w = 0; w < 8; w++) {
            a += scr[w * 4 + 0]; b += scr[w * 4 + 1];
            c += scr[w * 4 + 2]; d += scr[w * 4 + 3];
        }
        scr[0] = a; scr[1] = b; scr[2] = c; scr[3] = d;
    }
    __syncthreads();
    return make_float4(scr[0], scr[1], scr[2], scr[3]);
}

// ---- shared center-update tail (runs in last-finishing block) ----
__device__ __forceinline__ void update_tail(float co0, float co1, float* scr,
                                            int storeTot) {
    const int c = threadIdx.x;
    float4 r = blockReduce4(make_float4(co0 * co0, co1 * co1, 0.f, 0.f), scr);
    float no0 = sqrtf(r.x), no1 = sqrtf(r.y);
    float nc0 = 0.f, nc1 = 0.f, cd = 0.f;
#pragma unroll
    for (int b = 0; b < BB; b++) {
        float s1 = g_sums[(b * 2 + 1) * CC + c];
        float s0 = storeTot ? g_sums[(b * 2 + 0) * CC + c]
                            : (g_tot[b * CC + c] - s1);
        float n1 = g_counts[b * 2 + 1];
        float n0 = storeTot ? g_counts[b * 2 + 0] : ((float)NN - n1);
        if (storeTot) g_tot[b * CC + c] = s0 + s1;
        float ci0 = s0 / (n0 + 1.0f);
        float ci1 = s1 / (n1 + 1.0f);
        nc0 += ci0; nc1 += ci1;
        float4 q = blockReduce4(make_float4(ci0 * co0, ci0 * ci0, ci1 * co1, ci1 * ci1), scr);
        float den0 = fmaxf(sqrtf(q.y) * no0, 1e-8f);
        float den1 = fmaxf(sqrtf(q.w) * no1, 1e-8f);
        cd += 0.5f * (q.x / den0 + q.z / den1);
    }
    float cur = cd * 0.125f;
    nc0 *= 0.125f; nc1 *= 0.125f;
    float4 r2 = blockReduce4(make_float4(nc0 * nc0, nc1 * nc1, 0.f, 0.f), scr);
    float nn0 = fmaxf(sqrtf(r2.x), 1e-12f);
    float nn1 = fmaxf(sqrtf(r2.y), 1e-12f);
    g_centers[c] = nc0; g_centers[CC + c] = nc1;
    g_cn[c * 2 + 0] = nc0 / nn0;
    g_cn[c * 2 + 1] = nc1 / nn1;
#pragma unroll
    for (int jj = 0; jj < 16; jj++) g_sums[jj * CC + c] = 0.f;
    if (c < 16) g_counts[c] = 0.f;
    if (c == 0) {
        g_curdist = cur;
        if (cur < 0.01f) g_done = 1;
        g_ticket = 0u;
    }
}

// ======== iteration 0: R4 loop (64-px tiles, totals) + fused update ========
__global__ void __launch_bounds__(THREADS, 2) k_assign0(
        const float* __restrict__ F, const float* __restrict__ cinit) {
    __shared__ float s_part[16 * 129 + 8];
    __shared__ float s_cn[2 * CC];
    __shared__ float s_labs[TT];
    __shared__ float scr[32];
    __shared__ int s_cnt;
    __shared__ unsigned s_rank;

    const int tid = threadIdx.x;
    {   // normalize init centers per block (no k_init kernel)
        float c0 = cinit[tid], c1 = cinit[CC + tid];
        float4 r = blockReduce4(make_float4(c0 * c0, c1 * c1, 0.f, 0.f), scr);
        s_cn[tid * 2 + 0] = c0 / fmaxf(sqrtf(r.x), 1e-12f);
        s_cn[tid * 2 + 1] = c1 / fmaxf(sqrtf(r.y), 1e-12f);
    }
    if (tid == 0) s_cnt = 0;

    const int batch = blockIdx.x / BPB0;
    const int bi = blockIdx.x % BPB0;
    const int t0 = bi * TPB0;
    int t1 = t0 + TPB0; if (t1 > TILES0) t1 = TILES0;

    const int g = tid >> 4, j = tid & 15;
    const float* Fb = F + (long long)batch * CC * NN + (long long)g * NN + 4 * j;
    const float2* cn2 = (const float2*)s_cn;

    float acc1[16], accT[16];
#pragma unroll
    for (int k = 0; k < 16; k++) { acc1[k] = 0.f; accT[k] = 0.f; }
    int accCnt = 0;
    const int poff = 129 * g + 8 * j;
    __syncthreads();

    for (int t = t0; t < t1; t++) {
        const float* p = Fb + t * TT;
        float4 v[16];
        float dp[8];
#pragma unroll
        for (int q = 0; q < 8; q++) dp[q] = 0.f;
#pragma unroll
        for (int k = 0; k < 16; k++) {
            v[k] = __ldcs((const float4*)(p + (long long)k * (16 * NN)));
            float2 w = cn2[g + 16 * k];
            dp[0] = fmaf(v[k].x, w.x, dp[0]); dp[1] = fmaf(v[k].x, w.y, dp[1]);
            dp[2] = fmaf(v[k].y, w.x, dp[2]); dp[3] = fmaf(v[k].y, w.y, dp[3]);
            dp[4] = fmaf(v[k].z, w.x, dp[4]); dp[5] = fmaf(v[k].z, w.y, dp[5]);
            dp[6] = fmaf(v[k].w, w.x, dp[6]); dp[7] = fmaf(v[k].w, w.y, dp[7]);
            accT[k] += (v[k].x + v[k].y) + (v[k].z + v[k].w);
        }
        if (tid == 0) { accCnt += s_cnt; s_cnt = 0; }
#pragma unroll
        for (int q = 0; q < 8; q++)
            s_part[poff + ((q + j) & 7)] = dp[q];
        __syncthreads();

        if (tid < 128) {
            const int off = 8 * (tid >> 3) + (((tid & 7) + (tid >> 3)) & 7);
            float s = 0.f;
#pragma unroll
            for (int gg = 0; gg < 16; gg++) s += s_part[129 * gg + off];
            float o = __shfl_xor_sync(0xffffffffu, s, 1);
            int lab = 0;
            if (!(tid & 1)) {
                lab = (o > s) ? 1 : 0;
                int pidx = tid >> 1;
                s_labs[pidx] = (float)lab;
                g_labels[(long long)batch * NN + t * TT + pidx] = (unsigned char)lab;
            }
            unsigned bal = __ballot_sync(0xffffffffu, lab);
            if ((tid & 31) == 0) atomicAdd(&s_cnt, __popc(bal));
        }
        __syncthreads();

        float4 lb = *(const float4*)(s_labs + 4 * j);
#pragma unroll
        for (int k = 0; k < 16; k++) {
            float a = acc1[k];
            a = fmaf(lb.x, v[k].x, a); a = fmaf(lb.y, v[k].y, a);
            a = fmaf(lb.z, v[k].z, a); a = fmaf(lb.w, v[k].w, a);
            acc1[k] = a;
        }
    }
    __syncthreads();
    if (tid == 0) accCnt += s_cnt;

#pragma unroll
    for (int k = 0; k < 16; k++) {
        float a = acc1[k], s = accT[k];
#pragma unroll
        for (int o = 8; o > 0; o >>= 1) {
            a += __shfl_down_sync(0xffffffffu, a, o, 16);
            s += __shfl_down_sync(0xffffffffu, s, o, 16);
        }
        if (j == 0) {
            int c = g + 16 * k;
            atomicAdd(&g_sums[(batch * 2 + 1) * CC + c], a);
            atomicAdd(&g_sums[(batch * 2 + 0) * CC + c], s - a);
        }
    }
    if (tid == 0) {
        int npix = (t1 - t0) * TT;
        atomicAdd(&g_counts[batch * 2 + 1], (float)accCnt);
        atomicAdd(&g_counts[batch * 2 + 0], (float)(npix - accCnt));
    }

    __threadfence();
    __syncthreads();
    if (tid == 0) s_rank = atomicAdd(&g_ticket, 1u);
    __syncthreads();
    if (s_rank != (unsigned)(GRID0 - 1)) return;
    __threadfence();
    update_tail(cinit[tid], cinit[CC + tid], scr, /*storeTot=*/1);
}

// ======== iterations 1,2: light kernel (32-px tiles, cluster-1 only) =======
__global__ void __launch_bounds__(THREADS, 3) k_assign2(const float* __restrict__ F) {
    if (g_done) return;  // frozen after convergence
    __shared__ float s_part[8 * 72];    // [warp][8j + rot]
    __shared__ float s_cn[2 * CC];
    __shared__ float s_labs[T2];
    __shared__ float scr[32];
    __shared__ int s_cnt;
    __shared__ unsigned s_rank;

    const int tid = threadIdx.x;
    s_cn[tid] = g_cn[tid];
    s_cn[tid + 256] = g_cn[tid + 256];
    if (tid == 0) s_cnt = 0;

    const int batch = blockIdx.x / BPB2;
    const int bi = blockIdx.x % BPB2;
    const int t0 = bi * TPB2;
    int t1 = t0 + TPB2; if (t1 > TILES2) t1 = TILES2;

    const int g = tid >> 3;   // channels c = g + 32k, k<8
    const int j = tid & 7;    // pixels 4j..4j+3
    const int lane = tid & 31, w = tid >> 5;
    const int poff = w * 72 + 8 * j;
    const float* Fb = F + (long long)batch * CC * NN + (long long)g * NN + 4 * j;
    const float2* cn2 = (const float2*)s_cn;

    float acc1[8];
#pragma unroll
    for (int k = 0; k < 8; k++) acc1[k] = 0.f;
    int accCnt = 0;
    __syncthreads();

    for (int t = t0; t < t1; t++) {
        const float* p = Fb + t * T2;
        float4 v[8];
        float dp[8];
#pragma unroll
        for (int q = 0; q < 8; q++) dp[q] = 0.f;
#pragma unroll
        for (int k = 0; k < 8; k++) {
            v[k] = __ldcs((const float4*)(p + (long long)k * (32LL * NN)));
            float2 wc = cn2[g + 32 * k];
            dp[0] = fmaf(v[k].x, wc.x, dp[0]); dp[1] = fmaf(v[k].x, wc.y, dp[1]);
            dp[2] = fmaf(v[k].y, wc.x, dp[2]); dp[3] = fmaf(v[k].y, wc.y, dp[3]);
            dp[4] = fmaf(v[k].z, wc.x, dp[4]); dp[5] = fmaf(v[k].z, wc.y, dp[5]);
            dp[6] = fmaf(v[k].w, wc.x, dp[6]); dp[7] = fmaf(v[k].w, wc.y, dp[7]);
        }
        // pre-reduce the 4 in-warp channel groups (tid bits 3,4)
#pragma unroll
        for (int q = 0; q < 8; q++) {
            dp[q] += __shfl_xor_sync(0xffffffffu, dp[q], 8);
            dp[q] += __shfl_xor_sync(0xffffffffu, dp[q], 16);
        }
        if (tid == 0) { accCnt += s_cnt; s_cnt = 0; }   // race-free window
        if (lane < 8) {
#pragma unroll
            for (int q = 0; q < 8; q++)
                s_part[poff + ((q + j) & 7)] = dp[q];
        }
        __syncthreads();

        // labels: 64 threads, pp = pixel, kk = cluster
        if (tid < 64) {
            const int pp = tid >> 1, kk = tid & 1;
            const int jj = pp >> 2, q = (pp & 3) * 2 + kk;
            const int col = 8 * jj + ((q + jj) & 7);
            float s = 0.f;
#pragma unroll
            for (int ww = 0; ww < 8; ww++) s += s_part[ww * 72 + col];
            float o = __shfl_xor_sync(0xffffffffu, s, 1);
            int lab = 0;
            if (!kk) {
                lab = (o > s) ? 1 : 0;
                s_labs[pp] = (float)lab;
                g_labels[(long long)batch * NN + t * T2 + pp] = (unsigned char)lab;
            }
            unsigned bal = __ballot_sync(0xffffffffu, lab);
            if ((tid & 31) == 0) atomicAdd(&s_cnt, __popc(bal));
        }
        __syncthreads();

        float4 lb = *(const float4*)(s_labs + 4 * j);
#pragma unroll
        for (int k = 0; k < 8; k++) {
            float a = acc1[k];
            a = fmaf(lb.x, v[k].x, a); a = fmaf(lb.y, v[k].y, a);
            a = fmaf(lb.z, v[k].z, a); a = fmaf(lb.w, v[k].w, a);
            acc1[k] = a;
        }
    }
    __syncthreads();
    if (tid == 0) accCnt += s_cnt;

    // flush: reduce across the 8 j-lanes (contiguous within warp) + atomics
#pragma unroll
    for (int k = 0; k < 8; k++) {
        float a = acc1[k];
#pragma unroll
        for (int o = 4; o > 0; o >>= 1)
            a += __shfl_down_sync(0xffffffffu, a, o, 8);
        if (j == 0)
            atomicAdd(&g_sums[(batch * 2 + 1) * CC + g + 32 * k], a);
    }
    if (tid == 0) atomicAdd(&g_counts[batch * 2 + 1], (float)accCnt);

    __threadfence();
    __syncthreads();
    if (tid == 0) s_rank = atomicAdd(&g_ticket, 1u);
    __syncthreads();
    if (s_rank != (unsigned)(GRID2 - 1)) return;
    __threadfence();
    update_tail(g_centers[tid], g_centers[CC + tid], scr, /*storeTot=*/0);
}

// -------- finalize: write [centers | labels | onehot | cur_dist] --------
__global__ void k_final(float* __restrict__ out, long long outSize) {
    long long i = (long long)blockIdx.x * THREADS + threadIdx.x;
    if (i < 512 && i < outSize) out[i] = g_centers[i];
    if (i < (long long)BB * NN) {
        float lab = (float)g_labels[i];
        long long o1 = OFF_LABELS + i;
        long long o2 = OFF_ONEHOT + 2 * i;
        if (o1 < outSize) out[o1] = lab;
        if (o2 + 1 < outSize)
            *(float2*)(out + o2) = make_float2(1.0f - lab, lab);
    }
    if (i == 0) {
        if (OFF_CURDIST < outSize) out[OFF_CURDIST] = g_curdist;
        g_done = 0;   // reset for next graph replay
    }
}

extern "C" void kernel_launch(void* const* d_in, const int* in_sizes, int n_in,
                              void* d_out, int out_size) {
    const float* F = (const float*)d_in[0];
    const float* cinit = (const float*)d_in[1];
    if (n_in >= 2 && in_sizes[0] == 2 * CC) {  // tolerate swapped metadata order
        F = (const float*)d_in[1];
        cinit = (const float*)d_in[0];
    }
    k_assign0<<<GRID0, THREADS>>>(F, cinit);
    k_assign2<<<GRID2, THREADS>>>(F);
    k_assign2<<<GRID2, THREADS>>>(F);
    k_final<<<(BB * NN) / THREADS, THREADS>>>((float*)d_out, (long long)out_size);
}